// round 14
// baseline (speedup 1.0000x reference)
#include <cuda_runtime.h>

#define HN_B      2
#define HN_H      480
#define HN_W      640
#define HN_C      22
#define HN_HW     (HN_H * HN_W)          // 307200
#define HN_SKIP   20
#define HN_P      (HN_HW / HN_SKIP)      // 15360
#define HN_NSTEPS 200
#define HN_BC     (HN_B * HN_C)          // 44

#define HN_PLANEW  (HN_HW / 4)           // 76800 u32 words (4 px each, u8 bins)
#define HN_PLANE4  (HN_HW / 16)          // 19200 uint4 per plane
#define HN_AM_PT   5                     // uint4 per thread (argmax)
#define HN_AM_TILE (256 * HN_AM_PT)      // 1280 uint4 per block
#define HN_AM_BPP  (HN_PLANE4 / HN_AM_TILE) // 15 blocks per plane
#define HN_NVPL    42                    // voted planes (skip c==0)
#define HN_HISTBLK 600                   // argmax blocks that also do the histogram
#define HN_INLBLK  ((HN_B * HN_P + 255) / 256)  // 120

// Scratch (device globals; zero-initialized at module load; every kernel_launch
// restores them to zero, so graph replays are deterministic)
__device__ unsigned int       g_hough[HN_B * HN_C * HN_PLANEW];  // uint8 bins, packed
__device__ float4             g_pts[HN_B * HN_P];   // dnx, dny, z, label(bits)
__device__ unsigned long long g_vkey[HN_BC];        // (vmax<<32) | ~pk
__device__ float              g_zsum[HN_BC];
__device__ float              g_ninl[HN_BC];
__device__ unsigned int       g_counts[HN_BC];
__device__ unsigned int       g_ticket;

// map voted-plane index j in [0,42) -> bc, skipping bc==0 and bc==22
__device__ __forceinline__ int hn_plane(int j) { return (j < 21) ? (j + 1) : (j + 2); }

// PDL: wait until the upstream kernel's memory is visible.
__device__ __forceinline__ void hn_gdc_wait() {
    asm volatile("griddepcontrol.wait;" ::: "memory");
}

// packed f32x2 helpers (element-wise IEEE RN — identical to scalar __fmul_rn/__fadd_rn)
__device__ __forceinline__ unsigned long long hn_pack2(float lo, float hi) {
    unsigned long long d;
    asm("mov.b64 %0, {%1, %2};" : "=l"(d) : "f"(lo), "f"(hi));
    return d;
}
__device__ __forceinline__ void hn_unpack2(float& lo, float& hi, unsigned long long d) {
    asm("mov.b64 {%0, %1}, %2;" : "=f"(lo), "=f"(hi) : "l"(d));
}
__device__ __forceinline__ unsigned long long hn_mul2(unsigned long long a, unsigned long long b) {
    unsigned long long d;
    asm("mul.rn.f32x2 %0, %1, %2;" : "=l"(d) : "l"(a), "l"(b));
    return d;
}
__device__ __forceinline__ unsigned long long hn_add2(unsigned long long a, unsigned long long b) {
    unsigned long long d;
    asm("add.rn.f32x2 %0, %1, %2;" : "=l"(d) : "l"(a), "l"(b));
    return d;
}

// ---------------------------------------------------------------------------
// K1: hough voting ONLY (one warp per point). No smem, no block syncs.
//     Inner loop uses packed f32x2 math (same per-element RN semantics).
// ---------------------------------------------------------------------------
__global__ void hn_vote_kernel(const int* __restrict__ label_2d,
                               const float* __restrict__ vertex_pred) {
    int gwarp = (blockIdx.x * 256 + threadIdx.x) >> 5;
    int lane  = threadIdx.x & 31;
    if (gwarp >= HN_B * HN_P) return;

    int b = gwarp / HN_P;
    int p = gwarp % HN_P;
    int idx = p * HN_SKIP;
    float xs = (float)(idx % HN_W);
    float ys = (float)(idx / HN_W);

    int label = label_2d[b * HN_HW + idx];
    const float* vp = vertex_pred + ((size_t)(b * HN_HW + idx)) * (3 * HN_C) + label * 3;
    float dx = vp[0], dy = vp[1], z = vp[2];

    float nrm = __fadd_rn(__fsqrt_rn(__fadd_rn(__fmul_rn(dx, dx), __fmul_rn(dy, dy))), 1e-9f);
    float dnx = __fdiv_rn(dx, nrm);
    float dny = __fdiv_rn(dy, nrm);

    if (lane == 0) {
        float4 pt;
        pt.x = dnx; pt.y = dny; pt.z = z; pt.w = __int_as_float(label);
        g_pts[gwarp] = pt;
    }

    if (label <= 0) return;

    // conservative ray-exit bound: in-bounds after round-half-even needs
    // cx in [-0.5, 639.5), cy in [-0.5, 479.5); +-0.6 margin.
    // Per-step bounds check below remains authoritative.
    float tx = (dnx > 0.0f) ? (639.6f - xs) / dnx
             : (dnx < 0.0f) ? (-0.6f - xs) / dnx : 1e9f;
    float ty = (dny > 0.0f) ? (479.6f - ys) / dny
             : (dny < 0.0f) ? (-0.6f - ys) / dny : 1e9f;
    float thi = fminf(fminf(tx, ty), 800.0f);
    int nb = (int)(thi * 0.25f) + 1;                    // steps t=(i+1)*4 <= thi
    if (nb > HN_NSTEPS) nb = HN_NSTEPS;

    unsigned int* hbase = g_hough + (size_t)(b * HN_C + label) * HN_PLANEW;

    // packed state: (cx, cy) advanced by (dnx, dny) * 128 each strided iter.
    // t values are multiples of 4 <= 928 -> exact fp32, so the incremental
    // packed update is bit-identical to (i+1)*4 scalar recompute.
    float t0 = (float)(lane + 1) * 4.0f;
    unsigned long long xy   = hn_pack2(xs, ys);
    unsigned long long dxy  = hn_pack2(dnx, dny);
    unsigned long long step = hn_mul2(dxy, hn_pack2(128.0f, 128.0f));
    unsigned long long cxy  = hn_add2(xy, hn_mul2(dxy, hn_pack2(t0, t0)));

    #pragma unroll 2
    for (int i = lane; i < nb; i += 32) {
        float cx, cy;
        hn_unpack2(cx, cy, cxy);
        cxy = hn_add2(cxy, step);
        int cxi = __float2int_rn(cx);                   // round-half-even == jnp.round
        int cyi = __float2int_rn(cy);
        if ((unsigned)cxi < (unsigned)HN_W && (unsigned)cyi < (unsigned)HN_H) {
            atomicAdd(&hbase[cyi * (HN_W / 4) + (cxi >> 2)],
                      1u << ((cxi & 3) * 8));
        }
    }
}

// ---------------------------------------------------------------------------
// K2: argmax over the 42 voted planes + write-behind clear + fused label
//     histogram (first 600 of 630 blocks; label loads issued before the PDL
//     wait so they overlap the vote tail).
// ---------------------------------------------------------------------------
__global__ void hn_argmax_kernel(const int* __restrict__ label_2d) {
    int tile = blockIdx.y * HN_AM_BPP + blockIdx.x;     // 0..629
    __shared__ unsigned int s_cnt[HN_BC];
    bool do_hist = (tile < HN_HISTBLK);
    int4 l4;
    int  lb = 0;
    if (do_hist) {
        for (int i = threadIdx.x; i < HN_BC; i += 256) s_cnt[i] = 0u;
        int g4 = tile * 256 + threadIdx.x;              // < 153600
        l4 = reinterpret_cast<const int4*>(label_2d)[g4];
        lb = (g4 * 4) / HN_HW;                          // 4 labels share batch
    }

    int bc = hn_plane(blockIdx.y);
    uint4* h4 = reinterpret_cast<uint4*>(g_hough)
              + (size_t)bc * HN_PLANE4 + blockIdx.x * HN_AM_TILE;

    hn_gdc_wait();                                      // votes visible

    uint4 r[HN_AM_PT];
    #pragma unroll
    for (int o = 0; o < HN_AM_PT; o++)
        r[o] = h4[threadIdx.x + o * 256];               // all loads in flight

    if (do_hist) {
        __syncthreads();                                // s_cnt zeroed
        atomicAdd(&s_cnt[lb * HN_C + l4.x], 1u);
        atomicAdd(&s_cnt[lb * HN_C + l4.y], 1u);
        atomicAdd(&s_cnt[lb * HN_C + l4.z], 1u);
        atomicAdd(&s_cnt[lb * HN_C + l4.w], 1u);
    }

    // pass 1: per-thread max byte
    unsigned int m4 = 0u;
    #pragma unroll
    for (int o = 0; o < HN_AM_PT; o++) {
        m4 = __vmaxu4(m4, r[o].x);
        m4 = __vmaxu4(m4, r[o].y);
        m4 = __vmaxu4(m4, r[o].z);
        m4 = __vmaxu4(m4, r[o].w);
    }
    unsigned int tb = __vmaxu4(m4, m4 >> 16);
    tb = __vmaxu4(tb, tb >> 8);
    unsigned int bv = tb & 0xffu;
    unsigned int pat = bv * 0x01010101u;

    // pass 2: first pixel index (ascending) holding bv
    int bi = -1;
    #pragma unroll
    for (int o = 0; o < HN_AM_PT; o++) {
        int pb = (blockIdx.x * HN_AM_TILE + threadIdx.x + o * 256) * 16;
        unsigned int eq;
        eq = __vcmpeq4(r[o].x, pat);
        if (bi < 0 && eq) bi = pb + ((__ffs(eq) - 1) >> 3);
        eq = __vcmpeq4(r[o].y, pat);
        if (bi < 0 && eq) bi = pb + 4 + ((__ffs(eq) - 1) >> 3);
        eq = __vcmpeq4(r[o].z, pat);
        if (bi < 0 && eq) bi = pb + 8 + ((__ffs(eq) - 1) >> 3);
        eq = __vcmpeq4(r[o].w, pat);
        if (bi < 0 && eq) bi = pb + 12 + ((__ffs(eq) - 1) >> 3);
    }

    // clear tile for the next run (write-behind)
    uint4 z4 = make_uint4(0u, 0u, 0u, 0u);
    #pragma unroll
    for (int o = 0; o < HN_AM_PT; o++)
        h4[threadIdx.x + o * 256] = z4;

    unsigned long long key = ((unsigned long long)bv << 32) | (unsigned)(~bi);

    __shared__ unsigned long long sk[256];
    sk[threadIdx.x] = key;
    __syncthreads();
    #pragma unroll
    for (int s = 128; s > 0; s >>= 1) {
        if (threadIdx.x < s) {
            unsigned long long o = sk[threadIdx.x + s];
            if (o > sk[threadIdx.x]) sk[threadIdx.x] = o;
        }
        __syncthreads();
    }
    if (threadIdx.x == 0)
        atomicMax(&g_vkey[bc], sk[0]);

    if (do_hist) {
        for (int i = threadIdx.x; i < HN_BC; i += 256)
            if (s_cnt[i]) atomicAdd(&g_counts[i], s_cnt[i]);
    }
}

// ---------------------------------------------------------------------------
// K3: inlier accumulation + fused finalize in the last block (ticket pattern).
//     PDL: waits for argmax before reading g_vkey.
// ---------------------------------------------------------------------------
__global__ void hn_inlier_kernel(const float* __restrict__ extents,
                                 const float* __restrict__ meta,
                                 float* __restrict__ out) {
    __shared__ float s_z[HN_BC];
    __shared__ float s_n[HN_BC];
    __shared__ bool  s_last;
    for (int i = threadIdx.x; i < HN_BC; i += 256) { s_z[i] = 0.0f; s_n[i] = 0.0f; }

    hn_gdc_wait();                                      // vkeys + counts visible
    __syncthreads();

    int g = blockIdx.x * 256 + threadIdx.x;
    if (g < HN_B * HN_P) {
        int b = g / HN_P;
        int p = g % HN_P;
        int idx = p * HN_SKIP;
        float xs = (float)(idx % HN_W);
        float ys = (float)(idx / HN_W);

        float4 pt = g_pts[g];
        int label = __float_as_int(pt.w);
        if (label > 0) {
            int pk = (int)(~(unsigned)g_vkey[b * HN_C + label]);
            float pkx = (float)(pk % HN_W);
            float pky = (float)(pk / HN_W);
            float ddx = __fsub_rn(pkx, xs);
            float ddy = __fsub_rn(pky, ys);
            float nrm = __fadd_rn(__fsqrt_rn(__fadd_rn(__fmul_rn(ddx, ddx),
                                                       __fmul_rn(ddy, ddy))), 1e-9f);
            float dvx = __fdiv_rn(ddx, nrm);
            float dvy = __fdiv_rn(ddy, nrm);
            float dot = __fadd_rn(__fmul_rn(pt.x, dvx), __fmul_rn(pt.y, dvy));
            if (dot > 0.9f) {
                atomicAdd(&s_z[b * HN_C + label], pt.z);
                atomicAdd(&s_n[b * HN_C + label], 1.0f);
            }
        }
    }
    __syncthreads();
    for (int i = threadIdx.x; i < HN_BC; i += 256) {
        if (s_n[i] != 0.0f) {
            atomicAdd(&g_zsum[i], s_z[i]);
            atomicAdd(&g_ninl[i], s_n[i]);
        }
    }

    // ---- last-block finalize ----
    __threadfence();
    __syncthreads();
    if (threadIdx.x == 0)
        s_last = (atomicAdd(&g_ticket, 1u) == (unsigned)(gridDim.x - 1));
    __syncthreads();
    if (!s_last) return;

    int i = threadIdx.x;
    if (i < HN_BC) {
        int b = i / HN_C;
        int c = i % HN_C;

        float cnt   = (float)(*(volatile unsigned int*)&g_counts[i]);
        float vmask = (cnt >= 500.0f && c > 0) ? 1.0f : 0.0f;

        unsigned long long key = *(volatile unsigned long long*)&g_vkey[i];
        int pk = (c == 0) ? 0 : (int)(~(unsigned)key);
        float pkx  = (float)(pk % HN_W);
        float pky  = (float)(pk / HN_W);
        float vmax = (float)(unsigned)(key >> 32);

        float zs = *(volatile float*)&g_zsum[i];
        float ni = *(volatile float*)&g_ninl[i];
        float depth  = zs / fmaxf(ni, 1.0f);
        float z_safe = (fabsf(depth) > 0.001f) ? depth : 1.0f;

        float fx = meta[b * 48 + 0];
        float fy = meta[b * 48 + 4];
        float e0 = extents[c * 3 + 0], e1 = extents[c * 3 + 1], e2 = extents[c * 3 + 2];
        float diam = sqrtf(e0 * e0 + e1 * e1 + e2 * e2);
        float half_w = 0.5f * diam * fx / z_safe;
        float half_h = 0.5f * diam * fy / z_safe;

        float* o = out + (size_t)i * 14;
        o[0] = (float)b * vmask;
        o[1] = (float)c * vmask;
        o[2] = (pkx - half_w) * vmask;
        o[3] = (pky - half_h) * vmask;
        o[4] = (pkx + half_w) * vmask;
        o[5] = (pky + half_h) * vmask;
        o[6] = vmax * vmask;
        o[7] = vmask;          // quat = (1,0,0,0) * vmask
        o[8] = 0.0f;
        o[9] = 0.0f;
        o[10] = 0.0f;
        const float* K = meta + b * 48 + 9;   // Kinv row-major 3x3
        #pragma unroll
        for (int j = 0; j < 3; j++) {
            float ray = K[j * 3 + 0] * pkx + K[j * 3 + 1] * pky + K[j * 3 + 2];
            o[11 + j] = depth * ray * vmask;
        }

        // reset accumulators for the next graph replay
        g_vkey[i]   = 0ull;
        g_zsum[i]   = 0.0f;
        g_ninl[i]   = 0.0f;
        g_counts[i] = 0u;
    }
    if (threadIdx.x == 0) g_ticket = 0u;
}

// ---------------------------------------------------------------------------
extern "C" void kernel_launch(void* const* d_in, const int* in_sizes, int n_in,
                              void* d_out, int out_size) {
    const int*   label   = (const int*)d_in[0];
    const float* vp      = (const float*)d_in[1];
    const float* extents = (const float*)d_in[2];
    // d_in[3] = poses (unused by reference)
    const float* meta    = (const float*)d_in[4];
    float* out = (float*)d_out;

    // K1: vote only (plain launch)
    {
        int blocks = (HN_B * HN_P * 32 + 255) / 256;    // 3840
        hn_vote_kernel<<<blocks, 256>>>(label, vp);
    }

    cudaLaunchAttribute pdl[1];
    pdl[0].id = cudaLaunchAttributeProgrammaticStreamSerialization;
    pdl[0].val.programmaticStreamSerializationAllowed = 1;

    // K2: argmax + clear + label histogram (PDL after K1)
    {
        cudaLaunchConfig_t cfg = {};
        cfg.gridDim  = dim3(HN_AM_BPP, HN_NVPL);
        cfg.blockDim = dim3(256);
        cfg.attrs    = pdl;
        cfg.numAttrs = 1;
        cudaLaunchKernelEx(&cfg, hn_argmax_kernel, label);
    }
    // K3: inlier + last-block finalize (PDL after K2)
    {
        cudaLaunchConfig_t cfg = {};
        cfg.gridDim  = dim3(HN_INLBLK);
        cfg.blockDim = dim3(256);
        cfg.attrs    = pdl;
        cfg.numAttrs = 1;
        cudaLaunchKernelEx(&cfg, hn_inlier_kernel, extents, meta, out);
    }
}

// round 15
// speedup vs baseline: 1.0546x; 1.0546x over previous
#include <cuda_runtime.h>

#define HN_B      2
#define HN_H      480
#define HN_W      640
#define HN_C      22
#define HN_HW     (HN_H * HN_W)          // 307200
#define HN_SKIP   20
#define HN_P      (HN_HW / HN_SKIP)      // 15360
#define HN_NSTEPS 200
#define HN_BC     (HN_B * HN_C)          // 44

#define HN_PLANEW  (HN_HW / 4)           // 76800 u32 words (4 px each, u8 bins)
#define HN_PLANE4  (HN_HW / 16)          // 19200 uint4 per plane
#define HN_AM_PT   5                     // uint4 per thread (argmax)
#define HN_AM_TILE (256 * HN_AM_PT)      // 1280 uint4 per block
#define HN_AM_BPP  (HN_PLANE4 / HN_AM_TILE) // 15 blocks per plane
#define HN_NVPL    42                    // voted planes (skip c==0)
#define HN_HISTBLK 600                   // argmax blocks that also do the histogram
#define HN_INLBLK  ((HN_B * HN_P + 255) / 256)  // 120

// Scratch (device globals; zero-initialized at module load; every kernel_launch
// restores them to zero, so graph replays are deterministic)
__device__ unsigned int       g_hough[HN_B * HN_C * HN_PLANEW];  // uint8 bins, packed
__device__ float4             g_pts[HN_B * HN_P];   // dnx, dny, z, label(bits)
__device__ unsigned long long g_vkey[HN_BC];        // (vmax<<32) | ~pk
__device__ float              g_zsum[HN_BC];
__device__ float              g_ninl[HN_BC];
__device__ unsigned int       g_counts[HN_BC];
__device__ unsigned int       g_ticket;

// map voted-plane index j in [0,42) -> bc, skipping bc==0 and bc==22
__device__ __forceinline__ int hn_plane(int j) { return (j < 21) ? (j + 1) : (j + 2); }

// PDL: wait until the upstream kernel's memory is visible.
__device__ __forceinline__ void hn_gdc_wait() {
    asm volatile("griddepcontrol.wait;" ::: "memory");
}

// ---------------------------------------------------------------------------
// K1: hough voting ONLY (one warp per point). No smem, no block syncs.
//     At the spread-address RED throughput floor (confirmed by R5/R9/R14
//     instruction-count experiments all landing neutral).
// ---------------------------------------------------------------------------
__global__ void hn_vote_kernel(const int* __restrict__ label_2d,
                               const float* __restrict__ vertex_pred) {
    int gwarp = (blockIdx.x * 256 + threadIdx.x) >> 5;
    int lane  = threadIdx.x & 31;
    if (gwarp >= HN_B * HN_P) return;

    int b = gwarp / HN_P;
    int p = gwarp % HN_P;
    int idx = p * HN_SKIP;
    float xs = (float)(idx % HN_W);
    float ys = (float)(idx / HN_W);

    int label = label_2d[b * HN_HW + idx];
    const float* vp = vertex_pred + ((size_t)(b * HN_HW + idx)) * (3 * HN_C) + label * 3;
    float dx = vp[0], dy = vp[1], z = vp[2];

    float nrm = __fadd_rn(__fsqrt_rn(__fadd_rn(__fmul_rn(dx, dx), __fmul_rn(dy, dy))), 1e-9f);
    float dnx = __fdiv_rn(dx, nrm);
    float dny = __fdiv_rn(dy, nrm);

    if (lane == 0) {
        float4 pt;
        pt.x = dnx; pt.y = dny; pt.z = z; pt.w = __int_as_float(label);
        g_pts[gwarp] = pt;
    }

    if (label <= 0) return;

    // conservative ray-exit bound: in-bounds after round-half-even needs
    // cx in [-0.5, 639.5), cy in [-0.5, 479.5); +-0.6 margin.
    // Per-step bounds check below remains authoritative.
    float tx = (dnx > 0.0f) ? (639.6f - xs) / dnx
             : (dnx < 0.0f) ? (-0.6f - xs) / dnx : 1e9f;
    float ty = (dny > 0.0f) ? (479.6f - ys) / dny
             : (dny < 0.0f) ? (-0.6f - ys) / dny : 1e9f;
    float thi = fminf(fminf(tx, ty), 800.0f);
    int nb = (int)(thi * 0.25f) + 1;                    // steps t=(i+1)*4 <= thi
    if (nb > HN_NSTEPS) nb = HN_NSTEPS;

    unsigned int* hbase = g_hough + (size_t)(b * HN_C + label) * HN_PLANEW;
    // t kept incrementally: multiples of 4 <= 928 exact in fp32, so t += 128
    // is bit-identical to (i+1)*4 recompute.
    float t = (float)(lane + 1) * 4.0f;
    #pragma unroll 2
    for (int i = lane; i < nb; i += 32, t += 128.0f) {
        float cx = __fadd_rn(xs, __fmul_rn(dnx, t));
        float cy = __fadd_rn(ys, __fmul_rn(dny, t));
        int cxi = __float2int_rn(cx);                   // round-half-even == jnp.round
        int cyi = __float2int_rn(cy);
        if ((unsigned)cxi < (unsigned)HN_W && (unsigned)cyi < (unsigned)HN_H) {
            atomicAdd(&hbase[cyi * (HN_W / 4) + (cxi >> 2)],
                      1u << ((cxi & 3) * 8));
        }
    }
}

// ---------------------------------------------------------------------------
// K2: argmax over the 42 voted planes + write-behind clear + fused label
//     histogram (first 600 of 630 blocks; label loads issued BEFORE the PDL
//     wait so they overlap the vote tail).
// ---------------------------------------------------------------------------
__global__ void hn_argmax_kernel(const int* __restrict__ label_2d) {
    int tile = blockIdx.y * HN_AM_BPP + blockIdx.x;     // 0..629
    __shared__ unsigned int s_cnt[HN_BC];
    bool do_hist = (tile < HN_HISTBLK);
    int4 l4;
    int  lb = 0;
    if (do_hist) {
        for (int i = threadIdx.x; i < HN_BC; i += 256) s_cnt[i] = 0u;
        int g4 = tile * 256 + threadIdx.x;              // < 153600
        l4 = reinterpret_cast<const int4*>(label_2d)[g4];
        lb = (g4 * 4) / HN_HW;                          // 4 labels share batch
    }

    int bc = hn_plane(blockIdx.y);
    uint4* h4 = reinterpret_cast<uint4*>(g_hough)
              + (size_t)bc * HN_PLANE4 + blockIdx.x * HN_AM_TILE;

    hn_gdc_wait();                                      // votes visible

    uint4 r[HN_AM_PT];
    #pragma unroll
    for (int o = 0; o < HN_AM_PT; o++)
        r[o] = h4[threadIdx.x + o * 256];               // all loads in flight

    if (do_hist) {
        __syncthreads();                                // s_cnt zeroed
        atomicAdd(&s_cnt[lb * HN_C + l4.x], 1u);
        atomicAdd(&s_cnt[lb * HN_C + l4.y], 1u);
        atomicAdd(&s_cnt[lb * HN_C + l4.z], 1u);
        atomicAdd(&s_cnt[lb * HN_C + l4.w], 1u);
    }

    // pass 1: per-thread max byte
    unsigned int m4 = 0u;
    #pragma unroll
    for (int o = 0; o < HN_AM_PT; o++) {
        m4 = __vmaxu4(m4, r[o].x);
        m4 = __vmaxu4(m4, r[o].y);
        m4 = __vmaxu4(m4, r[o].z);
        m4 = __vmaxu4(m4, r[o].w);
    }
    unsigned int tb = __vmaxu4(m4, m4 >> 16);
    tb = __vmaxu4(tb, tb >> 8);
    unsigned int bv = tb & 0xffu;
    unsigned int pat = bv * 0x01010101u;

    // pass 2: first pixel index (ascending) holding bv
    int bi = -1;
    #pragma unroll
    for (int o = 0; o < HN_AM_PT; o++) {
        int pb = (blockIdx.x * HN_AM_TILE + threadIdx.x + o * 256) * 16;
        unsigned int eq;
        eq = __vcmpeq4(r[o].x, pat);
        if (bi < 0 && eq) bi = pb + ((__ffs(eq) - 1) >> 3);
        eq = __vcmpeq4(r[o].y, pat);
        if (bi < 0 && eq) bi = pb + 4 + ((__ffs(eq) - 1) >> 3);
        eq = __vcmpeq4(r[o].z, pat);
        if (bi < 0 && eq) bi = pb + 8 + ((__ffs(eq) - 1) >> 3);
        eq = __vcmpeq4(r[o].w, pat);
        if (bi < 0 && eq) bi = pb + 12 + ((__ffs(eq) - 1) >> 3);
    }

    // clear tile for the next run (write-behind)
    uint4 z4 = make_uint4(0u, 0u, 0u, 0u);
    #pragma unroll
    for (int o = 0; o < HN_AM_PT; o++)
        h4[threadIdx.x + o * 256] = z4;

    unsigned long long key = ((unsigned long long)bv << 32) | (unsigned)(~bi);

    __shared__ unsigned long long sk[256];
    sk[threadIdx.x] = key;
    __syncthreads();
    #pragma unroll
    for (int s = 128; s > 0; s >>= 1) {
        if (threadIdx.x < s) {
            unsigned long long o = sk[threadIdx.x + s];
            if (o > sk[threadIdx.x]) sk[threadIdx.x] = o;
        }
        __syncthreads();
    }
    if (threadIdx.x == 0)
        atomicMax(&g_vkey[bc], sk[0]);

    if (do_hist) {
        for (int i = threadIdx.x; i < HN_BC; i += 256)
            if (s_cnt[i]) atomicAdd(&g_counts[i], s_cnt[i]);
    }
}

// ---------------------------------------------------------------------------
// K3: inlier accumulation + fused finalize in the last block (ticket pattern).
//     PDL: waits for argmax before reading g_vkey.
// ---------------------------------------------------------------------------
__global__ void hn_inlier_kernel(const float* __restrict__ extents,
                                 const float* __restrict__ meta,
                                 float* __restrict__ out) {
    __shared__ float s_z[HN_BC];
    __shared__ float s_n[HN_BC];
    __shared__ bool  s_last;
    for (int i = threadIdx.x; i < HN_BC; i += 256) { s_z[i] = 0.0f; s_n[i] = 0.0f; }

    hn_gdc_wait();                                      // vkeys + counts visible
    __syncthreads();

    int g = blockIdx.x * 256 + threadIdx.x;
    if (g < HN_B * HN_P) {
        int b = g / HN_P;
        int p = g % HN_P;
        int idx = p * HN_SKIP;
        float xs = (float)(idx % HN_W);
        float ys = (float)(idx / HN_W);

        float4 pt = g_pts[g];
        int label = __float_as_int(pt.w);
        if (label > 0) {
            int pk = (int)(~(unsigned)g_vkey[b * HN_C + label]);
            float pkx = (float)(pk % HN_W);
            float pky = (float)(pk / HN_W);
            float ddx = __fsub_rn(pkx, xs);
            float ddy = __fsub_rn(pky, ys);
            float nrm = __fadd_rn(__fsqrt_rn(__fadd_rn(__fmul_rn(ddx, ddx),
                                                       __fmul_rn(ddy, ddy))), 1e-9f);
            float dvx = __fdiv_rn(ddx, nrm);
            float dvy = __fdiv_rn(ddy, nrm);
            float dot = __fadd_rn(__fmul_rn(pt.x, dvx), __fmul_rn(pt.y, dvy));
            if (dot > 0.9f) {
                atomicAdd(&s_z[b * HN_C + label], pt.z);
                atomicAdd(&s_n[b * HN_C + label], 1.0f);
            }
        }
    }
    __syncthreads();
    for (int i = threadIdx.x; i < HN_BC; i += 256) {
        if (s_n[i] != 0.0f) {
            atomicAdd(&g_zsum[i], s_z[i]);
            atomicAdd(&g_ninl[i], s_n[i]);
        }
    }

    // ---- last-block finalize ----
    __threadfence();
    __syncthreads();
    if (threadIdx.x == 0)
        s_last = (atomicAdd(&g_ticket, 1u) == (unsigned)(gridDim.x - 1));
    __syncthreads();
    if (!s_last) return;

    int i = threadIdx.x;
    if (i < HN_BC) {
        int b = i / HN_C;
        int c = i % HN_C;

        float cnt   = (float)(*(volatile unsigned int*)&g_counts[i]);
        float vmask = (cnt >= 500.0f && c > 0) ? 1.0f : 0.0f;

        unsigned long long key = *(volatile unsigned long long*)&g_vkey[i];
        int pk = (c == 0) ? 0 : (int)(~(unsigned)key);
        float pkx  = (float)(pk % HN_W);
        float pky  = (float)(pk / HN_W);
        float vmax = (float)(unsigned)(key >> 32);

        float zs = *(volatile float*)&g_zsum[i];
        float ni = *(volatile float*)&g_ninl[i];
        float depth  = zs / fmaxf(ni, 1.0f);
        float z_safe = (fabsf(depth) > 0.001f) ? depth : 1.0f;

        float fx = meta[b * 48 + 0];
        float fy = meta[b * 48 + 4];
        float e0 = extents[c * 3 + 0], e1 = extents[c * 3 + 1], e2 = extents[c * 3 + 2];
        float diam = sqrtf(e0 * e0 + e1 * e1 + e2 * e2);
        float half_w = 0.5f * diam * fx / z_safe;
        float half_h = 0.5f * diam * fy / z_safe;

        float* o = out + (size_t)i * 14;
        o[0] = (float)b * vmask;
        o[1] = (float)c * vmask;
        o[2] = (pkx - half_w) * vmask;
        o[3] = (pky - half_h) * vmask;
        o[4] = (pkx + half_w) * vmask;
        o[5] = (pky + half_h) * vmask;
        o[6] = vmax * vmask;
        o[7] = vmask;          // quat = (1,0,0,0) * vmask
        o[8] = 0.0f;
        o[9] = 0.0f;
        o[10] = 0.0f;
        const float* K = meta + b * 48 + 9;   // Kinv row-major 3x3
        #pragma unroll
        for (int j = 0; j < 3; j++) {
            float ray = K[j * 3 + 0] * pkx + K[j * 3 + 1] * pky + K[j * 3 + 2];
            o[11 + j] = depth * ray * vmask;
        }

        // reset accumulators for the next graph replay
        g_vkey[i]   = 0ull;
        g_zsum[i]   = 0.0f;
        g_ninl[i]   = 0.0f;
        g_counts[i] = 0u;
    }
    if (threadIdx.x == 0) g_ticket = 0u;
}

// ---------------------------------------------------------------------------
extern "C" void kernel_launch(void* const* d_in, const int* in_sizes, int n_in,
                              void* d_out, int out_size) {
    const int*   label   = (const int*)d_in[0];
    const float* vp      = (const float*)d_in[1];
    const float* extents = (const float*)d_in[2];
    // d_in[3] = poses (unused by reference)
    const float* meta    = (const float*)d_in[4];
    float* out = (float*)d_out;

    // K1: vote only (plain launch)
    {
        int blocks = (HN_B * HN_P * 32 + 255) / 256;    // 3840
        hn_vote_kernel<<<blocks, 256>>>(label, vp);
    }

    cudaLaunchAttribute pdl[1];
    pdl[0].id = cudaLaunchAttributeProgrammaticStreamSerialization;
    pdl[0].val.programmaticStreamSerializationAllowed = 1;

    // K2: argmax + clear + label histogram (PDL after K1)
    {
        cudaLaunchConfig_t cfg = {};
        cfg.gridDim  = dim3(HN_AM_BPP, HN_NVPL);
        cfg.blockDim = dim3(256);
        cfg.attrs    = pdl;
        cfg.numAttrs = 1;
        cudaLaunchKernelEx(&cfg, hn_argmax_kernel, label);
    }
    // K3: inlier + last-block finalize (PDL after K2)
    {
        cudaLaunchConfig_t cfg = {};
        cfg.gridDim  = dim3(HN_INLBLK);
        cfg.blockDim = dim3(256);
        cfg.attrs    = pdl;
        cfg.numAttrs = 1;
        cudaLaunchKernelEx(&cfg, hn_inlier_kernel, extents, meta, out);
    }
}